// round 1
// baseline (speedup 1.0000x reference)
#include <cuda_runtime.h>
#include <math.h>

#define B_   8
#define C_   192
#define TX_  512
#define TY_  2048
#define NEG_INF_F (-1e9f)

#define PATH_SZ ((size_t)B_*TY_*TX_)            /* 8388608 */
#define GATH_SZ ((size_t)B_*C_*TY_)             /* 3145728 */
#define MPA_OFF  (PATH_SZ)
#define LPA_OFF  (PATH_SZ + GATH_SZ)
#define LOSS_OFF (PATH_SZ + 2*GATH_SZ)
#define DUR_OFF  (LOSS_OFF + 1)

#define KL_BLOCKS (B_*C_*(TY_/256))             /* 12288 */
#define DP_SMEM (TY_*32*2 + TX_*4)              /* 133120 bytes */

// ---------------- scratch (__device__ globals; no runtime allocation) -------
__device__ float g_z2[B_*C_*TY_];               // -0.5*z^2
__device__ float g_s [B_*C_*TX_];               // exp(-2*logs_p)
__device__ float g_ms[B_*C_*TX_];               // m_p * s
__device__ float g_nc14[B_*TX_];                // nc1 + nc4
__device__ float g_negcent[(size_t)B_*TY_*TX_];
__device__ int   g_idx[B_*TY_];                 // backtrack path index, -1 inactive
__device__ int   g_speclen[B_];
__device__ float g_klpart[KL_BLOCKS];

// ---------------- prep: z2 ---------------------------------------------------
__global__ void k_prep_z2(const float* __restrict__ z_p) {
    int i = blockIdx.x * blockDim.x + threadIdx.x;     // over (B*C*TY)/4 float4s
    float4 z = ((const float4*)z_p)[i];
    float4 o;
    o.x = -0.5f * z.x * z.x;
    o.y = -0.5f * z.y * z.y;
    o.z = -0.5f * z.z * z.z;
    o.w = -0.5f * z.w * z.w;
    ((float4*)g_z2)[i] = o;
}

// ---------------- prep: s, ms, nc14 ------------------------------------------
__global__ void k_prep_b(const float* __restrict__ m_p,
                         const float* __restrict__ logs_p) {
    int x  = blockIdx.x * 32 + threadIdx.x;
    int b  = blockIdx.y;
    int ty = threadIdx.y;
    float part = 0.f;
    for (int c = ty; c < C_; c += 8) {
        int off = (b*C_ + c)*TX_ + x;
        float lp = logs_p[off];
        float m  = m_p[off];
        float s  = expf(-2.f * lp);
        float ms = m * s;
        g_s[off]  = s;
        g_ms[off] = ms;
        part += (-0.91893853320467274178f - lp - 0.5f*m*ms);
    }
    __shared__ float red[8][32];
    red[ty][threadIdx.x] = part;
    __syncthreads();
    if (ty == 0) {
        float t = 0.f;
        #pragma unroll
        for (int r = 0; r < 8; ++r) t += red[r][threadIdx.x];
        g_nc14[b*TX_ + x] = t;
    }
}

// ---------------- neg_cent GEMM: C[t][x] = sum_c z2*s + z*ms + nc14 ----------
__global__ void __launch_bounds__(256) k_negcent(const float* __restrict__ z_p) {
    __shared__ float As [8][128];
    __shared__ float A2s[8][128];
    __shared__ float Ss [8][64];
    __shared__ float Ms [8][64];

    int tid = threadIdx.x;
    int tx = tid & 15, ty = tid >> 4;
    int x0 = blockIdx.x * 64;
    int t0 = blockIdx.y * 128;
    int b  = blockIdx.z;

    float acc[8][4];
    #pragma unroll
    for (int i = 0; i < 8; ++i)
        #pragma unroll
        for (int j = 0; j < 4; ++j) acc[i][j] = 0.f;

    int am = tid & 127, ak = tid >> 7;   // A loaders: 2 k-rows base
    int sm = tid & 63,  sk = tid >> 6;   // B loaders: 4 k-rows base

    const float* zb  = z_p  + (size_t)b*C_*TY_;
    const float* z2b = g_z2 + (size_t)b*C_*TY_;
    const float* sb  = g_s  + b*C_*TX_;
    const float* msb = g_ms + b*C_*TX_;

    for (int c0 = 0; c0 < C_; c0 += 8) {
        #pragma unroll
        for (int r = 0; r < 4; ++r) {
            int k = ak + r*2;
            As [k][am] = zb [(size_t)(c0+k)*TY_ + t0 + am];
            A2s[k][am] = z2b[(size_t)(c0+k)*TY_ + t0 + am];
        }
        #pragma unroll
        for (int r = 0; r < 2; ++r) {
            int k = sk + r*4;
            Ss[k][sm] = sb [(c0+k)*TX_ + x0 + sm];
            Ms[k][sm] = msb[(c0+k)*TX_ + x0 + sm];
        }
        __syncthreads();
        #pragma unroll
        for (int k = 0; k < 8; ++k) {
            float a[8], a2[8], sv[4], mv[4];
            #pragma unroll
            for (int i = 0; i < 8; ++i) { a[i] = As[k][ty*8+i]; a2[i] = A2s[k][ty*8+i]; }
            #pragma unroll
            for (int j = 0; j < 4; ++j) { sv[j] = Ss[k][tx*4+j]; mv[j] = Ms[k][tx*4+j]; }
            #pragma unroll
            for (int i = 0; i < 8; ++i)
                #pragma unroll
                for (int j = 0; j < 4; ++j)
                    acc[i][j] = fmaf(a2[i], sv[j], fmaf(a[i], mv[j], acc[i][j]));
        }
        __syncthreads();
    }

    int xo = x0 + tx*4;
    float4 nc = *(const float4*)(g_nc14 + b*TX_ + xo);
    #pragma unroll
    for (int i = 0; i < 8; ++i) {
        int t = t0 + ty*8 + i;
        float4 o;
        o.x = acc[i][0] + nc.x;
        o.y = acc[i][1] + nc.y;
        o.z = acc[i][2] + nc.z;
        o.w = acc[i][3] + nc.w;
        *(float4*)(g_negcent + ((size_t)b*TY_ + t)*TX_ + xo) = o;
    }
}

// ---------------- MAS forward DP + backtrack ---------------------------------
struct RowBuf { float4 q0, q1, q2, q3; };

__device__ __forceinline__ void dp_load(RowBuf& rb, const float* base, int y, int lane) {
    const float4* rp = (const float4*)(base + (size_t)y*TX_ + lane*16);
    rb.q0 = rp[0]; rb.q1 = rp[1]; rb.q2 = rp[2]; rb.q3 = rp[3];
}

__device__ __forceinline__ void dp_step(int y, RowBuf& rb, float v[16],
                                        unsigned short* sdirs, int lane,
                                        const float* base) {
    float sc[16];
    sc[0]=rb.q0.x; sc[1]=rb.q0.y; sc[2]=rb.q0.z; sc[3]=rb.q0.w;
    sc[4]=rb.q1.x; sc[5]=rb.q1.y; sc[6]=rb.q1.z; sc[7]=rb.q1.w;
    sc[8]=rb.q2.x; sc[9]=rb.q2.y; sc[10]=rb.q2.z; sc[11]=rb.q2.w;
    sc[12]=rb.q3.x; sc[13]=rb.q3.y; sc[14]=rb.q3.z; sc[15]=rb.q3.w;

    if (y == 0) {
        #pragma unroll
        for (int i = 0; i < 16; ++i) v[i] = NEG_INF_F;
        if (lane == 0) v[0] = sc[0];
        sdirs[lane] = 0;
    } else {
        float pl = __shfl_up_sync(0xffffffffu, v[15], 1);
        if (lane == 0) pl = NEG_INF_F;
        unsigned m = 0;
        #pragma unroll
        for (int i = 15; i >= 1; --i) {
            float diag = v[i-1];
            if (diag > v[i]) m |= (1u << i);
            v[i] = sc[i] + fmaxf(v[i], diag);
        }
        if (pl > v[0]) m |= 1u;
        v[0] = sc[0] + fmaxf(v[0], pl);
        sdirs[y*32 + lane] = (unsigned short)m;
    }
    if (y + 4 < TY_) dp_load(rb, base, y + 4, lane);   // prefetch distance 4
}

__global__ void k_dp(const float* __restrict__ text_mask,
                     const float* __restrict__ spec_mask,
                     float* __restrict__ d_out) {
    extern __shared__ unsigned char smraw[];
    unsigned short* sdirs = (unsigned short*)smraw;                 // TY_*32
    int* sdur = (int*)(smraw + (size_t)TY_*32*sizeof(unsigned short)); // TX_

    int b = blockIdx.x;
    int lane = threadIdx.x;

    // lengths from masks
    float ts = 0.f, ss = 0.f;
    for (int i = lane; i < TX_; i += 32) ts += text_mask[b*TX_ + i];
    for (int i = lane; i < TY_; i += 32) ss += spec_mask[b*TY_ + i];
    #pragma unroll
    for (int o = 16; o > 0; o >>= 1) {
        ts += __shfl_xor_sync(0xffffffffu, ts, o);
        ss += __shfl_xor_sync(0xffffffffu, ss, o);
    }
    int text_len = (int)rintf(ts);
    int spec_len = (int)rintf(ss);

    for (int i = lane; i < TX_; i += 32) sdur[i] = 0;

    const float* base = g_negcent + (size_t)b*TY_*TX_;
    RowBuf r0, r1, r2, r3;
    dp_load(r0, base, 0, lane);
    dp_load(r1, base, 1, lane);
    dp_load(r2, base, 2, lane);
    dp_load(r3, base, 3, lane);

    float v[16];
    for (int y = 0; y < TY_; y += 4) {
        dp_step(y+0, r0, v, sdirs, lane, base);
        dp_step(y+1, r1, v, sdirs, lane, base);
        dp_step(y+2, r2, v, sdirs, lane, base);
        dp_step(y+3, r3, v, sdirs, lane, base);
    }
    __syncwarp();

    if (lane == 0) {
        int index = text_len - 1;
        for (int y = TY_ - 1; y >= 0; --y) {
            bool active = y < spec_len;
            g_idx[b*TY_ + y] = active ? index : -1;
            if (active) sdur[index] += 1;
            unsigned w = sdirs[y*32 + (index >> 4)];
            bool d_at = (w >> (index & 15)) & 1u;
            bool move = (index != 0) && ((index == y) || d_at);
            if (active && move) --index;
        }
        g_speclen[b] = spec_len;
    }
    __syncwarp();

    for (int i = lane; i < TX_; i += 32)
        d_out[DUR_OFF + (size_t)b*TX_ + i] = (float)sdur[i];
}

// ---------------- path one-hot ------------------------------------------------
__global__ void k_path(float* __restrict__ d_out) {
    int g = blockIdx.x * 256 + threadIdx.x;   // over B*TY*TX/4
    int x4  = (g & 127) << 2;
    int rem = g >> 7;
    int y = rem & (TY_ - 1);
    int b = rem >> 11;
    int idx = g_idx[b*TY_ + y];
    float4 o;
    o.x = (idx == x4 + 0) ? 1.f : 0.f;
    o.y = (idx == x4 + 1) ? 1.f : 0.f;
    o.z = (idx == x4 + 2) ? 1.f : 0.f;
    o.w = (idx == x4 + 3) ? 1.f : 0.f;
    ((float4*)d_out)[g] = o;
}

// ---------------- gather m_p_a / logs_p_a + fused KL partials -----------------
__global__ void k_gather(const float* __restrict__ z_p,
                         const float* __restrict__ m_p,
                         const float* __restrict__ logs_p,
                         const float* __restrict__ logs_q,
                         float* __restrict__ d_out) {
    int t = blockIdx.x * 256 + threadIdx.x;
    int c = blockIdx.y, b = blockIdx.z;
    int j = g_idx[b*TY_ + t];
    int row = b*C_ + c;
    float mv = 0.f, lv = 0.f, kl = 0.f;
    if (j >= 0) {
        mv = m_p[row*TX_ + j];
        lv = logs_p[row*TX_ + j];
        float z  = z_p[(size_t)row*TY_ + t];
        float lq = logs_q[(size_t)row*TY_ + t];
        float d  = z - mv;
        kl = lv - lq - 0.5f + 0.5f*d*d*expf(-2.f*lv);
    }
    d_out[MPA_OFF + (size_t)row*TY_ + t] = mv;
    d_out[LPA_OFF + (size_t)row*TY_ + t] = lv;

    __shared__ float red[256];
    red[threadIdx.x] = kl;
    __syncthreads();
    for (int s2 = 128; s2 > 0; s2 >>= 1) {
        if (threadIdx.x < s2) red[threadIdx.x] += red[threadIdx.x + s2];
        __syncthreads();
    }
    if (threadIdx.x == 0) {
        int bid = (blockIdx.z * gridDim.y + blockIdx.y) * gridDim.x + blockIdx.x;
        g_klpart[bid] = red[0];
    }
}

// ---------------- final loss reduction (deterministic) ------------------------
__global__ void k_loss(float* __restrict__ d_out) {
    int tid = threadIdx.x;
    float p = 0.f;
    for (int i = tid; i < KL_BLOCKS; i += 256) p += g_klpart[i];
    __shared__ float red[256];
    red[tid] = p;
    __syncthreads();
    for (int s2 = 128; s2 > 0; s2 >>= 1) {
        if (tid < s2) red[tid] += red[tid + s2];
        __syncthreads();
    }
    if (tid == 0) {
        float den = 0.f;
        for (int b = 0; b < B_; ++b) den += (float)g_speclen[b];
        d_out[LOSS_OFF] = red[0] / den;
    }
}

// ---------------- launch -------------------------------------------------------
extern "C" void kernel_launch(void* const* d_in, const int* in_sizes, int n_in,
                              void* d_out, int out_size) {
    const float* z_p       = (const float*)d_in[0];
    const float* m_p       = (const float*)d_in[1];
    const float* logs_p    = (const float*)d_in[2];
    const float* logs_q    = (const float*)d_in[3];
    const float* text_mask = (const float*)d_in[4];
    const float* spec_mask = (const float*)d_in[5];
    float* out = (float*)d_out;

    k_prep_z2<<<(B_*C_*TY_)/4/256, 256>>>(z_p);
    k_prep_b<<<dim3(TX_/32, B_), dim3(32, 8)>>>(m_p, logs_p);
    k_negcent<<<dim3(TX_/64, TY_/128, B_), 256>>>(z_p);

    cudaFuncSetAttribute(k_dp, cudaFuncAttributeMaxDynamicSharedMemorySize, DP_SMEM);
    k_dp<<<B_, 32, DP_SMEM>>>(text_mask, spec_mask, out);

    k_path<<<(int)(PATH_SZ/4/256), 256>>>(out);
    k_gather<<<dim3(TY_/256, C_, B_), 256>>>(z_p, m_p, logs_p, logs_q, out);
    k_loss<<<1, 256>>>(out);
}

// round 2
// speedup vs baseline: 1.1920x; 1.1920x over previous
#include <cuda_runtime.h>
#include <math.h>

#define B_   8
#define C_   192
#define TX_  512
#define TY_  2048
#define NEG_INF_F (-1e9f)

#define PATH_SZ ((size_t)B_*TY_*TX_)            /* 8388608 */
#define GATH_SZ ((size_t)B_*C_*TY_)             /* 3145728 */
#define MPA_OFF  (PATH_SZ)
#define LPA_OFF  (PATH_SZ + GATH_SZ)
#define LOSS_OFF (PATH_SZ + 2*GATH_SZ)
#define DUR_OFF  (LOSS_OFF + 1)

#define KL_BLOCKS (B_*C_*(TY_/256))             /* 12288 */
#define DP_SMEM (TY_*32*2 + TX_*4)              /* 133120 bytes */

// ---------------- scratch (__device__ globals; no runtime allocation) -------
__device__ float g_s [B_*C_*TX_];               // exp(-2*logs_p)
__device__ float g_ms[B_*C_*TX_];               // m_p * s
__device__ float g_nc14[B_*TX_];                // nc1 + nc4
__device__ float g_negcent[(size_t)B_*TY_*TX_];
__device__ int   g_idx[B_*TY_];                 // backtrack path index, -1 inactive
__device__ int   g_speclen[B_];
__device__ float g_klpart[KL_BLOCKS];

// ---------------- packed fp32x2 helpers (sm_100+) ----------------------------
__device__ __forceinline__ unsigned long long ffma2(unsigned long long a,
                                                    unsigned long long b,
                                                    unsigned long long c) {
    unsigned long long d;
    asm("fma.rn.f32x2 %0, %1, %2, %3;" : "=l"(d) : "l"(a), "l"(b), "l"(c));
    return d;
}
__device__ __forceinline__ unsigned long long dup2(float f) {
    unsigned long long d;
    unsigned r = __float_as_uint(f);
    asm("mov.b64 %0, {%1, %1};" : "=l"(d) : "r"(r));
    return d;
}
__device__ __forceinline__ void unpk2(unsigned long long v, float& lo, float& hi) {
    unsigned a, b;
    asm("mov.b64 {%0, %1}, %2;" : "=r"(a), "=r"(b) : "l"(v));
    lo = __uint_as_float(a);
    hi = __uint_as_float(b);
}

// ---------------- prep: s, ms, nc14 ------------------------------------------
__global__ void k_prep_b(const float* __restrict__ m_p,
                         const float* __restrict__ logs_p) {
    int x  = blockIdx.x * 32 + threadIdx.x;
    int b  = blockIdx.y;
    int ty = threadIdx.y;
    float part = 0.f;
    for (int c = ty; c < C_; c += 8) {
        int off = (b*C_ + c)*TX_ + x;
        float lp = logs_p[off];
        float m  = m_p[off];
        float s  = expf(-2.f * lp);
        float ms = m * s;
        g_s[off]  = s;
        g_ms[off] = ms;
        part += (-0.91893853320467274178f - lp - 0.5f*m*ms);
    }
    __shared__ float red[8][32];
    red[ty][threadIdx.x] = part;
    __syncthreads();
    if (ty == 0) {
        float t = 0.f;
        #pragma unroll
        for (int r = 0; r < 8; ++r) t += red[r][threadIdx.x];
        g_nc14[b*TX_ + x] = t;
    }
}

// ---------------- neg_cent GEMM (FFMA2): C[t][x] = sum_c z2*s + z*ms + nc14 --
#define BM 128
#define BN 128

__global__ void __launch_bounds__(256, 1) k_negcent(const float* __restrict__ z_p) {
    __shared__ __align__(16) float As [8][BM];   // z
    __shared__ __align__(16) float A2s[8][BM];   // -0.5*z*z
    __shared__ __align__(16) float Ss [8][BN];   // s
    __shared__ __align__(16) float Ms [8][BN];   // m*s

    int tid = threadIdx.x;
    int tx = tid & 15, ty = tid >> 4;            // 16 x-groups, 16 t-groups
    int x0 = blockIdx.x * BN;
    int t0 = blockIdx.y * BM;
    int b  = blockIdx.z;

    int lk = tid >> 5;            // loader k-row 0..7
    int li = (tid & 31) * 4;      // loader col 0..124

    const float* zb  = z_p  + (size_t)b*C_*TY_ + t0;
    const float* sb  = g_s  + b*C_*TX_ + x0;
    const float* msb = g_ms + b*C_*TX_ + x0;

    unsigned long long acc[4][8];
    #pragma unroll
    for (int i = 0; i < 4; ++i)
        #pragma unroll
        for (int j = 0; j < 8; ++j) acc[i][j] = 0ull;

    for (int c0 = 0; c0 < C_; c0 += 8) {
        float4 z4 = *(const float4*)(zb  + (size_t)(c0+lk)*TY_ + li);
        float4 s4 = *(const float4*)(sb  + (c0+lk)*TX_ + li);
        float4 m4 = *(const float4*)(msb + (c0+lk)*TX_ + li);
        *(float4*)&As[lk][li] = z4;
        float4 z2;
        z2.x = -0.5f*z4.x*z4.x; z2.y = -0.5f*z4.y*z4.y;
        z2.z = -0.5f*z4.z*z4.z; z2.w = -0.5f*z4.w*z4.w;
        *(float4*)&A2s[lk][li] = z2;
        *(float4*)&Ss[lk][li]  = s4;
        *(float4*)&Ms[lk][li]  = m4;
        __syncthreads();

        #pragma unroll
        for (int k = 0; k < 8; ++k) {
            // A pairs along t (free packing from consecutive floats)
            ulonglong2 aA = *(const ulonglong2*)&As [k][ty*8];
            ulonglong2 aB = *(const ulonglong2*)&As [k][ty*8+4];
            ulonglong2 qA = *(const ulonglong2*)&A2s[k][ty*8];
            ulonglong2 qB = *(const ulonglong2*)&A2s[k][ty*8+4];
            unsigned long long az[4]  = {aA.x, aA.y, aB.x, aB.y};
            unsigned long long az2[4] = {qA.x, qA.y, qB.x, qB.y};

            float4 sA = *(const float4*)&Ss[k][tx*8];
            float4 sB = *(const float4*)&Ss[k][tx*8+4];
            float4 mA = *(const float4*)&Ms[k][tx*8];
            float4 mB = *(const float4*)&Ms[k][tx*8+4];
            unsigned long long sd[8] = {dup2(sA.x), dup2(sA.y), dup2(sA.z), dup2(sA.w),
                                        dup2(sB.x), dup2(sB.y), dup2(sB.z), dup2(sB.w)};
            unsigned long long md[8] = {dup2(mA.x), dup2(mA.y), dup2(mA.z), dup2(mA.w),
                                        dup2(mB.x), dup2(mB.y), dup2(mB.z), dup2(mB.w)};

            #pragma unroll
            for (int i = 0; i < 4; ++i)
                #pragma unroll
                for (int j = 0; j < 8; ++j)
                    acc[i][j] = ffma2(az2[i], sd[j], ffma2(az[i], md[j], acc[i][j]));
        }
        __syncthreads();
    }

    // epilogue: add nc14, write two t-rows per acc pair
    int xo = x0 + tx*8;
    float4 ncA = *(const float4*)(g_nc14 + b*TX_ + xo);
    float4 ncB = *(const float4*)(g_nc14 + b*TX_ + xo + 4);
    float nc[8] = {ncA.x, ncA.y, ncA.z, ncA.w, ncB.x, ncB.y, ncB.z, ncB.w};

    #pragma unroll
    for (int i = 0; i < 4; ++i) {
        float lo[8], hi[8];
        #pragma unroll
        for (int j = 0; j < 8; ++j) unpk2(acc[i][j], lo[j], hi[j]);
        int tA = t0 + ty*8 + i*2;
        float* o0 = g_negcent + ((size_t)b*TY_ + tA)*TX_ + xo;
        float* o1 = o0 + TX_;
        float4 w;
        w.x = lo[0]+nc[0]; w.y = lo[1]+nc[1]; w.z = lo[2]+nc[2]; w.w = lo[3]+nc[3];
        *(float4*)o0 = w;
        w.x = lo[4]+nc[4]; w.y = lo[5]+nc[5]; w.z = lo[6]+nc[6]; w.w = lo[7]+nc[7];
        *(float4*)(o0+4) = w;
        w.x = hi[0]+nc[0]; w.y = hi[1]+nc[1]; w.z = hi[2]+nc[2]; w.w = hi[3]+nc[3];
        *(float4*)o1 = w;
        w.x = hi[4]+nc[4]; w.y = hi[5]+nc[5]; w.z = hi[6]+nc[6]; w.w = hi[7]+nc[7];
        *(float4*)(o1+4) = w;
    }
}

// ---------------- MAS forward DP + backtrack ---------------------------------
struct RowBuf { float4 q0, q1, q2, q3; };

__device__ __forceinline__ void dp_load(RowBuf& rb, const float* base, int y, int lane) {
    const float4* rp = (const float4*)(base + (size_t)y*TX_ + lane*16);
    rb.q0 = rp[0]; rb.q1 = rp[1]; rb.q2 = rp[2]; rb.q3 = rp[3];
}

__device__ __forceinline__ void dp_step(int y, RowBuf& rb, float v[16],
                                        unsigned short* sdirs, int lane,
                                        const float* base) {
    float sc[16];
    sc[0]=rb.q0.x; sc[1]=rb.q0.y; sc[2]=rb.q0.z; sc[3]=rb.q0.w;
    sc[4]=rb.q1.x; sc[5]=rb.q1.y; sc[6]=rb.q1.z; sc[7]=rb.q1.w;
    sc[8]=rb.q2.x; sc[9]=rb.q2.y; sc[10]=rb.q2.z; sc[11]=rb.q2.w;
    sc[12]=rb.q3.x; sc[13]=rb.q3.y; sc[14]=rb.q3.z; sc[15]=rb.q3.w;

    if (y == 0) {
        #pragma unroll
        for (int i = 0; i < 16; ++i) v[i] = NEG_INF_F;
        if (lane == 0) v[0] = sc[0];
        sdirs[lane] = 0;
    } else {
        float pl = __shfl_up_sync(0xffffffffu, v[15], 1);
        if (lane == 0) pl = NEG_INF_F;
        unsigned m = 0;
        #pragma unroll
        for (int i = 15; i >= 1; --i) {
            float diag = v[i-1];
            bool p = diag > v[i];
            if (p) m |= (1u << i);
            v[i] = sc[i] + (p ? diag : v[i]);
        }
        bool p0 = pl > v[0];
        if (p0) m |= 1u;
        v[0] = sc[0] + (p0 ? pl : v[0]);
        sdirs[y*32 + lane] = (unsigned short)m;
    }
    if (y + 4 < TY_) dp_load(rb, base, y + 4, lane);   // prefetch distance 4
}

__global__ void k_dp(const float* __restrict__ text_mask,
                     const float* __restrict__ spec_mask,
                     float* __restrict__ d_out) {
    extern __shared__ unsigned char smraw[];
    unsigned short* sdirs = (unsigned short*)smraw;                 // TY_*32
    int* sdur = (int*)(smraw + (size_t)TY_*32*sizeof(unsigned short)); // TX_

    int b = blockIdx.x;
    int lane = threadIdx.x;

    // lengths from masks
    float ts = 0.f, ss = 0.f;
    for (int i = lane; i < TX_; i += 32) ts += text_mask[b*TX_ + i];
    for (int i = lane; i < TY_; i += 32) ss += spec_mask[b*TY_ + i];
    #pragma unroll
    for (int o = 16; o > 0; o >>= 1) {
        ts += __shfl_xor_sync(0xffffffffu, ts, o);
        ss += __shfl_xor_sync(0xffffffffu, ss, o);
    }
    int text_len = (int)rintf(ts);
    int spec_len = (int)rintf(ss);

    for (int i = lane; i < TX_; i += 32) sdur[i] = 0;

    const float* base = g_negcent + (size_t)b*TY_*TX_;
    RowBuf r0, r1, r2, r3;
    dp_load(r0, base, 0, lane);
    dp_load(r1, base, 1, lane);
    dp_load(r2, base, 2, lane);
    dp_load(r3, base, 3, lane);

    float v[16];
    for (int y = 0; y < TY_; y += 4) {
        dp_step(y+0, r0, v, sdirs, lane, base);
        dp_step(y+1, r1, v, sdirs, lane, base);
        dp_step(y+2, r2, v, sdirs, lane, base);
        dp_step(y+3, r3, v, sdirs, lane, base);
    }
    __syncwarp();

    if (lane == 0) {
        int idx = text_len - 1;
        unsigned w_cur = sdirs[(TY_-1)*32 + (idx >> 4)];
        int* gb = g_idx + b*TY_;
        for (int y = TY_ - 1; y >= 0; --y) {
            // prefetch both candidate words for row y-1 (off the serial chain)
            unsigned wa = 0, wb = 0;
            if (y > 0) {
                wa = sdirs[(y-1)*32 + (idx >> 4)];
                int im = (idx > 0) ? idx - 1 : 0;
                wb = sdirs[(y-1)*32 + (im >> 4)];
            }
            bool active = y < spec_len;
            gb[y] = active ? idx : -1;
            if (active) sdur[idx] += 1;
            bool d_at = (w_cur >> (idx & 15)) & 1u;
            bool move = (idx != 0) && ((idx == y) || d_at);
            if (active && move) { --idx; w_cur = wb; }
            else                {        w_cur = wa; }
        }
        g_speclen[b] = spec_len;
    }
    __syncwarp();

    for (int i = lane; i < TX_; i += 32)
        d_out[DUR_OFF + (size_t)b*TX_ + i] = (float)sdur[i];
}

// ---------------- path one-hot ------------------------------------------------
__global__ void k_path(float* __restrict__ d_out) {
    int g = blockIdx.x * 256 + threadIdx.x;   // over B*TY*TX/4
    int x4  = (g & 127) << 2;
    int rem = g >> 7;
    int y = rem & (TY_ - 1);
    int b = rem >> 11;
    int idx = g_idx[b*TY_ + y];
    float4 o;
    o.x = (idx == x4 + 0) ? 1.f : 0.f;
    o.y = (idx == x4 + 1) ? 1.f : 0.f;
    o.z = (idx == x4 + 2) ? 1.f : 0.f;
    o.w = (idx == x4 + 3) ? 1.f : 0.f;
    ((float4*)d_out)[g] = o;
}

// ---------------- gather m_p_a / logs_p_a + fused KL partials -----------------
__global__ void k_gather(const float* __restrict__ z_p,
                         const float* __restrict__ m_p,
                         const float* __restrict__ logs_p,
                         const float* __restrict__ logs_q,
                         float* __restrict__ d_out) {
    int t = blockIdx.x * 256 + threadIdx.x;
    int c = blockIdx.y, b = blockIdx.z;
    int j = g_idx[b*TY_ + t];
    int row = b*C_ + c;
    float mv = 0.f, lv = 0.f, kl = 0.f;
    if (j >= 0) {
        mv = m_p[row*TX_ + j];
        lv = logs_p[row*TX_ + j];
        float z  = z_p[(size_t)row*TY_ + t];
        float lq = logs_q[(size_t)row*TY_ + t];
        float d  = z - mv;
        kl = lv - lq - 0.5f + 0.5f*d*d*expf(-2.f*lv);
    }
    d_out[MPA_OFF + (size_t)row*TY_ + t] = mv;
    d_out[LPA_OFF + (size_t)row*TY_ + t] = lv;

    __shared__ float red[256];
    red[threadIdx.x] = kl;
    __syncthreads();
    for (int s2 = 128; s2 > 0; s2 >>= 1) {
        if (threadIdx.x < s2) red[threadIdx.x] += red[threadIdx.x + s2];
        __syncthreads();
    }
    if (threadIdx.x == 0) {
        int bid = (blockIdx.z * gridDim.y + blockIdx.y) * gridDim.x + blockIdx.x;
        g_klpart[bid] = red[0];
    }
}

// ---------------- final loss reduction (deterministic) ------------------------
__global__ void k_loss(float* __restrict__ d_out) {
    int tid = threadIdx.x;
    float p = 0.f;
    for (int i = tid; i < KL_BLOCKS; i += 256) p += g_klpart[i];
    __shared__ float red[256];
    red[tid] = p;
    __syncthreads();
    for (int s2 = 128; s2 > 0; s2 >>= 1) {
        if (tid < s2) red[tid] += red[tid + s2];
        __syncthreads();
    }
    if (tid == 0) {
        float den = 0.f;
        for (int b = 0; b < B_; ++b) den += (float)g_speclen[b];
        d_out[LOSS_OFF] = red[0] / den;
    }
}

// ---------------- launch -------------------------------------------------------
extern "C" void kernel_launch(void* const* d_in, const int* in_sizes, int n_in,
                              void* d_out, int out_size) {
    const float* z_p       = (const float*)d_in[0];
    const float* m_p       = (const float*)d_in[1];
    const float* logs_p    = (const float*)d_in[2];
    const float* logs_q    = (const float*)d_in[3];
    const float* text_mask = (const float*)d_in[4];
    const float* spec_mask = (const float*)d_in[5];
    float* out = (float*)d_out;

    k_prep_b<<<dim3(TX_/32, B_), dim3(32, 8)>>>(m_p, logs_p);
    k_negcent<<<dim3(TX_/BN, TY_/BM, B_), 256>>>(z_p);

    cudaFuncSetAttribute(k_dp, cudaFuncAttributeMaxDynamicSharedMemorySize, DP_SMEM);
    k_dp<<<B_, 32, DP_SMEM>>>(text_mask, spec_mask, out);

    k_path<<<(int)(PATH_SZ/4/256), 256>>>(out);
    k_gather<<<dim3(TY_/256, C_, B_), 256>>>(z_p, m_p, logs_p, logs_q, out);
    k_loss<<<1, 256>>>(out);
}